// round 16
// baseline (speedup 1.0000x reference)
#include <cuda_runtime.h>
#include <cuda_fp16.h>
#include <cstdint>

#define L_SEQ   2048
#define NBATCH  2
#define NHEADS  16
#define HDIM    64
#define EMBED   1024
// Q pre-scale: 1/sqrt(1024) * log2(e)  -> S comes out in log2 domain
#define QSCALE  (0.03125f * 1.44269504f)
#define KT      64
#define NT      (L_SEQ / KT)
#define ONES2   0x3C003C00u   // fp16x2 {1.0, 1.0}

// ---------------- scratch (device globals; no allocation allowed) -------------
__device__ __half g_q[(size_t)NBATCH * NHEADS * L_SEQ * HDIM];
__device__ __half g_k[(size_t)NBATCH * NHEADS * L_SEQ * HDIM];
__device__ __half g_v[(size_t)NBATCH * NHEADS * L_SEQ * HDIM];
// fragment-ordered fp16 AND-masks: [n][qt128][kti][tid2][kk] as uint4
__device__ uint4 g_mf[(size_t)NBATCH * 16 * 32 * 256 * 4];

// ---------------- helpers -----------------------------------------------------
__device__ __forceinline__ unsigned pack2(float lo, float hi) {
    unsigned r;
    asm("cvt.rn.f16x2.f32 %0, %1, %2;" : "=r"(r) : "f"(hi), "f"(lo));
    return r;
}
__device__ __forceinline__ void mma16(float (&d)[4], const unsigned* a,
                                      unsigned b0, unsigned b1) {
    asm volatile(
        "mma.sync.aligned.m16n8k16.row.col.f32.f16.f16.f32 "
        "{%0,%1,%2,%3}, {%4,%5,%6,%7}, {%8,%9}, {%0,%1,%2,%3};"
        : "+f"(d[0]), "+f"(d[1]), "+f"(d[2]), "+f"(d[3])
        : "r"(a[0]), "r"(a[1]), "r"(a[2]), "r"(a[3]), "r"(b0), "r"(b1));
}
__device__ __forceinline__ void mma16h(unsigned& d0, unsigned& d1,
                                       const unsigned* a,
                                       unsigned b0, unsigned b1) {
    asm volatile(
        "mma.sync.aligned.m16n8k16.row.col.f16.f16.f16.f16 "
        "{%0,%1}, {%2,%3,%4,%5}, {%6,%7}, {%0,%1};"
        : "+r"(d0), "+r"(d1)
        : "r"(a[0]), "r"(a[1]), "r"(a[2]), "r"(a[3]), "r"(b0), "r"(b1));
}
__device__ __forceinline__ void mma16h_z(unsigned& d0, unsigned& d1,
                                         const unsigned* a,
                                         unsigned b0, unsigned b1) {
    asm volatile(
        "mma.sync.aligned.m16n8k16.row.col.f16.f16.f16.f16 "
        "{%0,%1}, {%2,%3,%4,%5}, {%6,%7}, {%8,%9};"
        : "=r"(d0), "=r"(d1)
        : "r"(a[0]), "r"(a[1]), "r"(a[2]), "r"(a[3]), "r"(b0), "r"(b1),
          "r"(0u), "r"(0u));
}
__device__ __forceinline__ void ex2h2(unsigned& x) {
    asm("ex2.approx.f16x2 %0, %0;" : "+r"(x));
}
__device__ __forceinline__ void ldm4(unsigned (&r)[4], uint32_t addr) {
    asm volatile("ldmatrix.sync.aligned.m8n8.x4.shared.b16 {%0,%1,%2,%3}, [%4];"
                 : "=r"(r[0]), "=r"(r[1]), "=r"(r[2]), "=r"(r[3]) : "r"(addr));
}
__device__ __forceinline__ void cpa16(uint32_t dst, const void* src) {
    asm volatile("cp.async.cg.shared.global [%0], [%1], 16;" :: "r"(dst), "l"(src));
}
#define CP_COMMIT()  asm volatile("cp.async.commit_group;")
#define CP_WAIT(N)   asm volatile("cp.async.wait_group %0;" :: "n"(N))

__device__ __forceinline__ unsigned u4c(const uint4& m, int j) {
    return j == 0 ? m.x : j == 1 ? m.y : j == 2 ? m.z : m.w;   // j compile-time under unroll
}

// ---- fragment-order half offsets (validated rounds 2-14) ---------------------
__device__ __forceinline__ int qa_off(int r, int c) {
    int lane = ((r & 7) << 2) | ((c & 7) >> 1);
    int reg  = ((r >> 3) & 1) | (((c >> 3) & 1) << 1);
    return ((r >> 4) << 10) + ((c >> 4) << 8) + (lane << 3) + (reg << 1) + (c & 1);
}
__device__ __forceinline__ int kb_off(int r, int c) {
    int lane = ((r & 7) << 2) | ((c & 7) >> 1);
    return ((c >> 4) << 10) + ((r >> 4) << 8) + (lane << 3) +
           (((r >> 3) & 1) << 2) + (((c >> 3) & 1) << 1) + (c & 1);
}
__device__ __forceinline__ int vb_off(int s, int d) {
    int lane = ((d & 7) << 2) | ((s & 7) >> 1);
    return ((s >> 4) << 10) + ((d >> 4) << 8) + (lane << 3) +
           (((d >> 3) & 1) << 2) + (((s >> 3) & 1) << 1) + (s & 1);
}

// ---------------- kernel 1: QKV projections + fragment-ordered mask -----------
#define XH_S 72
__global__ __launch_bounds__(256) void proj_kernel(
    const float* __restrict__ vals, const float* __restrict__ keys,
    const float* __restrict__ qrys,
    const float* __restrict__ Wv, const float* __restrict__ Wk,
    const float* __restrict__ Wq, const int* __restrict__ mask)
{
    __shared__ __half Xh[64 * XH_S];
    __shared__ __half Wh[64 * XH_S];
    __shared__ __half Ps[4096];

    const int lt = blockIdx.x, h = blockIdx.y, n = blockIdx.z;
    const int l0 = lt * 64;
    const int tid = threadIdx.x, warp = tid >> 5, lane = tid & 31;
    const int grp = lane >> 2, t = tid & 3;
    const int r0 = (warp & 3) * 16, n0 = (warp >> 2) * 32;

    // ---- fused mask fragment generation ----
    {
        const int unit = ((lt << 4) | h) * 256 + tid;
        const int qtm = unit >> 13;
        const int ktm = (unit >> 8) & 31;
        const int t2  = unit & 255;
        const int w2 = t2 >> 5, l2v = t2 & 31, g2 = l2v >> 2, tt = l2v & 3;
        const int raw = qtm * 128 + w2 * 16 + g2;
        const int* ma = mask + (size_t)n * L_SEQ * L_SEQ + (size_t)raw * L_SEQ
                             + ktm * 64 + 2 * tt;
        const int* mbp = ma + 8 * L_SEQ;
        uint4* dst = g_mf + (((size_t)(n * 16 + qtm) * 32 + ktm) * 256 + t2) * 4;
        #pragma unroll
        for (int kk = 0; kk < 4; ++kk) {
            int2 va  = *(const int2*)(ma  + kk * 16);
            int2 vb  = *(const int2*)(mbp + kk * 16);
            int2 va8 = *(const int2*)(ma  + kk * 16 + 8);
            int2 vb8 = *(const int2*)(mbp + kk * 16 + 8);
            uint4 f;
            f.x = (va.x  ? 0xFFFFu : 0u) | (va.y  ? 0xFFFF0000u : 0u);
            f.y = (vb.x  ? 0xFFFFu : 0u) | (vb.y  ? 0xFFFF0000u : 0u);
            f.z = (va8.x ? 0xFFFFu : 0u) | (va8.y ? 0xFFFF0000u : 0u);
            f.w = (vb8.x ? 0xFFFFu : 0u) | (vb8.y ? 0xFFFF0000u : 0u);
            dst[kk] = f;
        }
    }

    const float* Xsrc[3] = {vals, keys, qrys};
    const float* Wsrc[3] = {Wv, Wk, Wq};

    const uint32_t xh_u = (uint32_t)__cvta_generic_to_shared(Xh);
    const uint32_t wh_u = (uint32_t)__cvta_generic_to_shared(Wh);
    const int arow = r0 + (lane & 15), acol8 = (lane >> 4) << 3;
    const int brow = (lane & 7) | ((lane & 16) >> 1), bcol8 = lane & 8;

    for (int p = 0; p < 3; ++p) {
        for (int i = tid * 4; i < 4096; i += 1024) {
            int r = i >> 6, c = i & 63;
            float4 x = *(const float4*)(Xsrc[p] +
                ((size_t)(n * L_SEQ + l0 + r)) * EMBED + h * HDIM + c);
            *(unsigned*)(Xh + r * XH_S + c)     = pack2(x.x, x.y);
            *(unsigned*)(Xh + r * XH_S + c + 2) = pack2(x.z, x.w);
            float4 w = *(const float4*)(Wsrc[p] + i);
            *(unsigned*)(Wh + r * XH_S + c)     = pack2(w.x, w.y);
            *(unsigned*)(Wh + r * XH_S + c + 2) = pack2(w.z, w.w);
        }
        __syncthreads();

        float acc[4][4] = {};
        #pragma unroll
        for (int kk = 0; kk < 4; ++kk) {
            unsigned a[4];
            ldm4(a, xh_u + (arow * XH_S + kk * 16 + acol8) * 2);
            #pragma unroll
            for (int jp = 0; jp < 2; ++jp) {
                unsigned b[4];
                ldm4(b, wh_u + ((n0 + jp * 16 + brow) * XH_S + kk * 16 + bcol8) * 2);
                mma16(acc[jp * 2],     a, b[0], b[1]);
                mma16(acc[jp * 2 + 1], a, b[2], b[3]);
            }
        }
        __syncthreads();

        const int r1 = r0 + grp, r2 = r1 + 8;
        #pragma unroll
        for (int nb = 0; nb < 4; ++nb) {
            const int c0 = n0 + nb * 8 + 2 * t;
            if (p == 0) {
                Ps[vb_off(r1, c0)]     = __float2half_rn(acc[nb][0]);
                Ps[vb_off(r1, c0 + 1)] = __float2half_rn(acc[nb][1]);
                Ps[vb_off(r2, c0)]     = __float2half_rn(acc[nb][2]);
                Ps[vb_off(r2, c0 + 1)] = __float2half_rn(acc[nb][3]);
            } else if (p == 1) {
                *(unsigned*)(Ps + kb_off(r1, c0)) = pack2(acc[nb][0], acc[nb][1]);
                *(unsigned*)(Ps + kb_off(r2, c0)) = pack2(acc[nb][2], acc[nb][3]);
            } else {
                *(unsigned*)(Ps + qa_off(r1, c0)) =
                    pack2(acc[nb][0] * QSCALE, acc[nb][1] * QSCALE);
                *(unsigned*)(Ps + qa_off(r2, c0)) =
                    pack2(acc[nb][2] * QSCALE, acc[nb][3] * QSCALE);
            }
        }
        __syncthreads();

        const size_t hb = (size_t)(n * NHEADS + h) * L_SEQ * HDIM;
        __half* dst;
        if (p == 0)      dst = g_v + hb + (size_t)lt * 4096;
        else if (p == 1) dst = g_k + hb + (size_t)lt * 4096;
        else             dst = g_q + hb + (size_t)(l0 >> 7) * 8192 + ((l0 & 64) ? 4096 : 0);
        for (int i = tid; i < 512; i += 256)
            ((uint4*)dst)[i] = ((const uint4*)Ps)[i];
        __syncthreads();
    }
}

// ---------------- kernel 2: fp16 flash attention, S(t+1)/softmax(t) pipeline --
// smem bytes: KB[3] 8192 each | VB[3] 8192 each = 49152
#define OFF_KB  0
#define OFF_VB  24576
#define ATTN_SMEM 49152

__global__ __launch_bounds__(64, 4) void attn_kernel(float* __restrict__ out)
{
    extern __shared__ char smc[];
    const int qt = blockIdx.x;            // 64-row tile index (0..31)
    const int h = blockIdx.y, n = blockIdx.z;
    const int qt128 = qt >> 1;
    const int tid = threadIdx.x, warp = tid >> 5, lane = tid & 31;
    const int grp = lane >> 2, t4 = lane & 3;
    const int bg0 = (qt & 1) * 4 + 2 * warp;   // first 16-row block id in qt128

    const __half* qg = g_q + ((size_t)(n * NHEADS + h) * 16 + qt128) * 8192;
    const __half* kg = g_k + (size_t)(n * NHEADS + h) * L_SEQ * HDIM;
    const __half* vg = g_v + (size_t)(n * NHEADS + h) * L_SEQ * HDIM;
    const uint4* mf0 = g_mf + ((size_t)(n * 16 + qt128) * 32 * 256 + bg0 * 32 + lane) * 4;
    const uint4* mf1 = mf0 + 32 * 4;

    const uint32_t sb = (uint32_t)__cvta_generic_to_shared(smc);

    // prologue: G0 = {K0, V0}; G1 = {K1, V1}
    #pragma unroll
    for (int j = 0; j < 8; ++j) {
        cpa16(sb + OFF_KB + (tid + j * 64) * 16, (const uint4*)kg + tid + j * 64);
        cpa16(sb + OFF_VB + (tid + j * 64) * 16, (const uint4*)vg + tid + j * 64);
    }
    CP_COMMIT();
    #pragma unroll
    for (int j = 0; j < 8; ++j) {
        cpa16(sb + OFF_KB + 8192 + (tid + j * 64) * 16, (const uint4*)(kg + 4096) + tid + j * 64);
        cpa16(sb + OFF_VB + 8192 + (tid + j * 64) * 16, (const uint4*)(vg + 4096) + tid + j * 64);
    }
    CP_COMMIT();

    // Q fragments for both row blocks
    unsigned qa[2][4][4];
    #pragma unroll
    for (int b = 0; b < 2; ++b) {
        const uint4* qg4 = (const uint4*)qg + (bg0 + b) * 128 + lane;
        #pragma unroll
        for (int kk = 0; kk < 4; ++kk) {
            uint4 v = qg4[kk * 32];
            qa[b][kk][0] = v.x; qa[b][kk][1] = v.y; qa[b][kk][2] = v.z; qa[b][kk][3] = v.w;
        }
    }

    float o[2][8][4];
    #pragma unroll
    for (int b = 0; b < 2; ++b)
        #pragma unroll
        for (int j = 0; j < 8; ++j)
            o[b][j][0] = o[b][j][1] = o[b][j][2] = o[b][j][3] = 0.f;
    float ld[2][4] = {};

    // S double buffer: su[ph][block][16]
    unsigned su[2][2][16];

    // ---- preheader: S(0) into su[0] (K buffer 0) ----
    CP_WAIT(1);           // G0 complete (G1 may be in flight)
    __syncthreads();
    {
        const uint4* kb4 = (const uint4*)(smc + OFF_KB) + lane;
        #pragma unroll
        for (int kk = 0; kk < 4; ++kk) {
            #pragma unroll
            for (int jp = 0; jp < 4; ++jp) {
                uint4 bv = kb4[kk * 128 + jp * 32];
                #pragma unroll
                for (int b = 0; b < 2; ++b) {
                    if (kk == 0) {
                        mma16h_z(su[0][b][4 * jp],     su[0][b][4 * jp + 1], qa[b][0], bv.x, bv.y);
                        mma16h_z(su[0][b][4 * jp + 2], su[0][b][4 * jp + 3], qa[b][0], bv.z, bv.w);
                    } else {
                        mma16h(su[0][b][4 * jp],     su[0][b][4 * jp + 1], qa[b][kk], bv.x, bv.y);
                        mma16h(su[0][b][4 * jp + 2], su[0][b][4 * jp + 3], qa[b][kk], bv.z, bv.w);
                    }
                }
            }
        }
    }

    int bV = 0;   // V buffer for tile t ; K buffer for t+1 = (bV+1)%3 ; prefetch = (bV+2)%3
    for (int kti = 0; kti < NT; kti += 2) {
        #pragma unroll
        for (int ph = 0; ph < 2; ++ph) {
            const int t = kti + ph;
            unsigned (*cur)[16] = su[ph];
            unsigned (*nxt)[16] = su[ph ^ 1];

            CP_WAIT(0);       // K/V for t and t+1 fully resident
            __syncthreads();  // visible to all; buffer (t+2)%3 free for reuse

            const int bK = (bV == 2) ? 0 : bV + 1;       // K buf for tile t+1 (wraps to stale data at t=NT-1; unused)
            const int bP = (bK == 2) ? 0 : bK + 1;
            if (t + 2 < NT) {
                const uint4* k2 = (const uint4*)(kg + (size_t)(t + 2) * 4096);
                const uint4* v2 = (const uint4*)(vg + (size_t)(t + 2) * 4096);
                const uint32_t kd = sb + OFF_KB + bP * 8192;
                const uint32_t vd = sb + OFF_VB + bP * 8192;
                #pragma unroll
                for (int j = 0; j < 8; ++j) {
                    cpa16(kd + (tid + j * 64) * 16, k2 + tid + j * 64);
                    cpa16(vd + (tid + j * 64) * 16, v2 + tid + j * 64);
                }
            }
            CP_COMMIT();

            // masks for tile t
            uint4 mk0[4], mk1[4];
            #pragma unroll
            for (int kk = 0; kk < 4; ++kk) {
                mk0[kk] = mf0[(size_t)t * 1024 + kk];
                mk1[kk] = mf1[(size_t)t * 1024 + kk];
            }

            const uint4* kb4 = (const uint4*)(smc + OFF_KB + bK * 8192) + lane;
            const uint4* vb4 = (const uint4*)(smc + OFF_VB + bV * 8192) + lane;

            // ---- interleaved: S(t+1) -> nxt  ||  ex2+mask on cur ----
            // (independent streams: tensor pipe vs MUFU/ALU; 4 mma then 2 ex2
            //  per step keeps the in-order warp always holding tensor work)
            #pragma unroll
            for (int kk = 0; kk < 4; ++kk) {
                #pragma unroll
                for (int jp = 0; jp < 4; ++jp) {
                    uint4 bv = kb4[kk * 128 + jp * 32];
                    #pragma unroll
                    for (int b = 0; b < 2; ++b) {
                        if (kk == 0) {
                            mma16h_z(nxt[b][4 * jp],     nxt[b][4 * jp + 1], qa[b][0], bv.x, bv.y);
                            mma16h_z(nxt[b][4 * jp + 2], nxt[b][4 * jp + 3], qa[b][0], bv.z, bv.w);
                        } else {
                            mma16h(nxt[b][4 * jp],     nxt[b][4 * jp + 1], qa[b][kk], bv.x, bv.y);
                            mma16h(nxt[b][4 * jp + 2], nxt[b][4 * jp + 3], qa[b][kk], bv.z, bv.w);
                        }
                    }
                    // two ex2 + masks on cur (index kk*4+jp covers all 16 once)
                    const int i = kk * 4 + jp;
                    ex2h2(cur[0][i]); cur[0][i] &= u4c(mk0[kk], jp);
                    ex2h2(cur[1][i]); cur[1][i] &= u4c(mk1[kk], jp);
                }
            }

            // ---- PV(t) with cur ; row sums via ones-mma ----
            #pragma unroll
            for (int g = 0; g < 4; ++g) {
                #pragma unroll
                for (int jp = 0; jp < 4; ++jp) {
                    uint4 bv = vb4[g * 128 + jp * 32];
                    #pragma unroll
                    for (int b = 0; b < 2; ++b) {
                        mma16(o[b][jp * 2],     cur[b] + 4 * g, bv.x, bv.y);
                        mma16(o[b][jp * 2 + 1], cur[b] + 4 * g, bv.z, bv.w);
                    }
                }
                mma16(ld[0], cur[0] + 4 * g, ONES2, ONES2);
                mma16(ld[1], cur[1] + 4 * g, ONES2, ONES2);
            }

            bV = (bV == 2) ? 0 : bV + 1;
        }
    }

    // ---- epilogue per row block ----
    const int q0 = qt128 * 128;
    #pragma unroll
    for (int b = 0; b < 2; ++b) {
        const int ra = (bg0 + b) * 16 + grp;
        const float inv1 = 1.f / ld[b][0], inv2 = 1.f / ld[b][2];
        float* ob1 = out + ((size_t)(n * L_SEQ + q0 + ra)) * EMBED + h * HDIM;
        float* ob2 = out + ((size_t)(n * L_SEQ + q0 + ra + 8)) * EMBED + h * HDIM;
        #pragma unroll
        for (int j = 0; j < 8; ++j) {
            int c0 = j * 8 + 2 * t4;
            *(float2*)(ob1 + c0) = make_float2(o[b][j][0] * inv1, o[b][j][1] * inv1);
            *(float2*)(ob2 + c0) = make_float2(o[b][j][2] * inv2, o[b][j][3] * inv2);
        }
    }
}

// ---------------- launch ------------------------------------------------------
extern "C" void kernel_launch(void* const* d_in, const int* in_sizes, int n_in,
                              void* d_out, int out_size)
{
    const float* values  = (const float*)d_in[0];
    const float* keys    = (const float*)d_in[1];
    const float* queries = (const float*)d_in[2];
    const int*   mask    = (const int*)d_in[3];
    const float* Wv      = (const float*)d_in[4];
    const float* Wk      = (const float*)d_in[5];
    const float* Wq      = (const float*)d_in[6];
    float* out = (float*)d_out;

    cudaFuncSetAttribute(attn_kernel, cudaFuncAttributeMaxDynamicSharedMemorySize, ATTN_SMEM);

    proj_kernel<<<dim3(L_SEQ / 64, NHEADS, NBATCH), 256>>>(
        values, keys, queries, Wv, Wk, Wq, mask);
    attn_kernel<<<dim3(L_SEQ / 64, NHEADS, NBATCH), 64, ATTN_SMEM>>>(out);
}

// round 17
// speedup vs baseline: 1.0002x; 1.0002x over previous
#include <cuda_runtime.h>
#include <cuda_fp16.h>
#include <cstdint>

#define L_SEQ   2048
#define NBATCH  2
#define NHEADS  16
#define HDIM    64
#define EMBED   1024
// Q pre-scale: 1/sqrt(1024) * log2(e)  -> S comes out in log2 domain
#define QSCALE  (0.03125f * 1.44269504f)
#define KT      64
#define NT      (L_SEQ / KT)
#define ONES2   0x3C003C00u   // fp16x2 {1.0, 1.0}

// ---------------- scratch (device globals; no allocation allowed) -------------
__device__ __half g_q[(size_t)NBATCH * NHEADS * L_SEQ * HDIM];
__device__ __half g_k[(size_t)NBATCH * NHEADS * L_SEQ * HDIM];
__device__ __half g_v[(size_t)NBATCH * NHEADS * L_SEQ * HDIM];
// fragment-ordered fp16 AND-masks: [n][qt128][kti][tid2][kk] as uint4
__device__ uint4 g_mf[(size_t)NBATCH * 16 * 32 * 256 * 4];

// ---------------- helpers -----------------------------------------------------
__device__ __forceinline__ unsigned pack2(float lo, float hi) {
    unsigned r;
    asm("cvt.rn.f16x2.f32 %0, %1, %2;" : "=r"(r) : "f"(hi), "f"(lo));
    return r;
}
__device__ __forceinline__ void mma16(float (&d)[4], const unsigned* a,
                                      unsigned b0, unsigned b1) {
    asm volatile(
        "mma.sync.aligned.m16n8k16.row.col.f32.f16.f16.f32 "
        "{%0,%1,%2,%3}, {%4,%5,%6,%7}, {%8,%9}, {%0,%1,%2,%3};"
        : "+f"(d[0]), "+f"(d[1]), "+f"(d[2]), "+f"(d[3])
        : "r"(a[0]), "r"(a[1]), "r"(a[2]), "r"(a[3]), "r"(b0), "r"(b1));
}
__device__ __forceinline__ void mma16h(unsigned& d0, unsigned& d1,
                                       const unsigned* a,
                                       unsigned b0, unsigned b1) {
    asm volatile(
        "mma.sync.aligned.m16n8k16.row.col.f16.f16.f16.f16 "
        "{%0,%1}, {%2,%3,%4,%5}, {%6,%7}, {%0,%1};"
        : "+r"(d0), "+r"(d1)
        : "r"(a[0]), "r"(a[1]), "r"(a[2]), "r"(a[3]), "r"(b0), "r"(b1));
}
__device__ __forceinline__ void mma16h_z(unsigned& d0, unsigned& d1,
                                         const unsigned* a,
                                         unsigned b0, unsigned b1) {
    asm volatile(
        "mma.sync.aligned.m16n8k16.row.col.f16.f16.f16.f16 "
        "{%0,%1}, {%2,%3,%4,%5}, {%6,%7}, {%8,%9};"
        : "=r"(d0), "=r"(d1)
        : "r"(a[0]), "r"(a[1]), "r"(a[2]), "r"(a[3]), "r"(b0), "r"(b1),
          "r"(0u), "r"(0u));
}
__device__ __forceinline__ void ex2h2(unsigned& x) {
    asm("ex2.approx.f16x2 %0, %0;" : "+r"(x));
}
__device__ __forceinline__ void ldm4(unsigned (&r)[4], uint32_t addr) {
    asm volatile("ldmatrix.sync.aligned.m8n8.x4.shared.b16 {%0,%1,%2,%3}, [%4];"
                 : "=r"(r[0]), "=r"(r[1]), "=r"(r[2]), "=r"(r[3]) : "r"(addr));
}
__device__ __forceinline__ void cpa16(uint32_t dst, const void* src) {
    asm volatile("cp.async.cg.shared.global [%0], [%1], 16;" :: "r"(dst), "l"(src));
}
#define CP_COMMIT()  asm volatile("cp.async.commit_group;")
#define CP_WAIT(N)   asm volatile("cp.async.wait_group %0;" :: "n"(N))

// ---- fragment-order half offsets (validated rounds 2-16) ---------------------
__device__ __forceinline__ int qa_off(int r, int c) {
    int lane = ((r & 7) << 2) | ((c & 7) >> 1);
    int reg  = ((r >> 3) & 1) | (((c >> 3) & 1) << 1);
    return ((r >> 4) << 10) + ((c >> 4) << 8) + (lane << 3) + (reg << 1) + (c & 1);
}
__device__ __forceinline__ int kb_off(int r, int c) {
    int lane = ((r & 7) << 2) | ((c & 7) >> 1);
    return ((c >> 4) << 10) + ((r >> 4) << 8) + (lane << 3) +
           (((r >> 3) & 1) << 2) + (((c >> 3) & 1) << 1) + (c & 1);
}
__device__ __forceinline__ int vb_off(int s, int d) {
    int lane = ((d & 7) << 2) | ((s & 7) >> 1);
    return ((s >> 4) << 10) + ((d >> 4) << 8) + (lane << 3) +
           (((d >> 3) & 1) << 2) + (((s >> 3) & 1) << 1) + (s & 1);
}

// ---------------- kernel 1: QKV projections + smem-staged mask fragments ------
#define XH_S 72
#define MS_S 66                                   // int stride, conflict-free gather
#define PRJ_SMEM_A (128 * MS_S * 4)               // 33792 B mask tile
#define PRJ_SMEM_B ((2 * 64 * XH_S + 4096) * 2)   // Xh + Wh + Ps = 26624 B
#define PRJ_SMEM   (PRJ_SMEM_A > PRJ_SMEM_B ? PRJ_SMEM_A : PRJ_SMEM_B)

__global__ __launch_bounds__(256) void proj_kernel(
    const float* __restrict__ vals, const float* __restrict__ keys,
    const float* __restrict__ qrys,
    const float* __restrict__ Wv, const float* __restrict__ Wk,
    const float* __restrict__ Wq, const int* __restrict__ mask)
{
    extern __shared__ char psm_raw[];

    const int lt = blockIdx.x, h = blockIdx.y, n = blockIdx.z;
    const int l0 = lt * 64;
    const int tid = threadIdx.x, warp = tid >> 5, lane = tid & 31;
    const int grp = lane >> 2, t = tid & 3;
    const int r0 = (warp & 3) * 16, n0 = (warp >> 2) * 32;

    // ---- phase A: mask fragments via coalesced smem staging ----
    // This block's 256 units = one (qtm, ktm) pair -> one 128x64 int mask tile.
    {
        int* Ms = (int*)psm_raw;
        const int lh  = lt * 16 + h;
        const int qtm = lh >> 5;          // 128-row q tile
        const int ktm = lh & 31;          // 64-col k tile
        const int* msrc = mask + (size_t)n * L_SEQ * L_SEQ
                               + (size_t)(qtm * 128) * L_SEQ + ktm * 64;
        // coalesced load: 2048 int4 (16 per row), 8 per thread
        for (int i = tid; i < 2048; i += 256) {
            const int row = i >> 4, c4 = i & 15;
            int4 v = *(const int4*)(msrc + (size_t)row * L_SEQ + c4 * 4);
            int* d = Ms + row * MS_S + c4 * 4;
            d[0] = v.x; d[1] = v.y; d[2] = v.z; d[3] = v.w;
        }
        __syncthreads();

        const int w2 = tid >> 5, l2v = tid & 31, g2 = l2v >> 2, tt = l2v & 3;
        const int* ma  = Ms + (w2 * 16 + g2) * MS_S + 2 * tt;
        const int* mbp = ma + 8 * MS_S;
        uint4* dst = g_mf + (((size_t)(n * 16 + qtm) * 32 + ktm) * 256 + tid) * 4;
        #pragma unroll
        for (int kk = 0; kk < 4; ++kk) {
            int2 va  = *(const int2*)(ma  + kk * 16);
            int2 vb  = *(const int2*)(mbp + kk * 16);
            int2 va8 = *(const int2*)(ma  + kk * 16 + 8);
            int2 vb8 = *(const int2*)(mbp + kk * 16 + 8);
            uint4 f;
            f.x = (va.x  ? 0xFFFFu : 0u) | (va.y  ? 0xFFFF0000u : 0u);
            f.y = (vb.x  ? 0xFFFFu : 0u) | (vb.y  ? 0xFFFF0000u : 0u);
            f.z = (va8.x ? 0xFFFFu : 0u) | (va8.y ? 0xFFFF0000u : 0u);
            f.w = (vb8.x ? 0xFFFFu : 0u) | (vb8.y ? 0xFFFF0000u : 0u);
            dst[kk] = f;
        }
        __syncthreads();   // smem handed over to phase B
    }

    // ---- phase B: QKV projections (same smem reused) ----
    __half* Xh = (__half*)psm_raw;
    __half* Wh = Xh + 64 * XH_S;
    __half* Ps = Wh + 64 * XH_S;

    const float* Xsrc[3] = {vals, keys, qrys};
    const float* Wsrc[3] = {Wv, Wk, Wq};

    const uint32_t xh_u = (uint32_t)__cvta_generic_to_shared(Xh);
    const uint32_t wh_u = (uint32_t)__cvta_generic_to_shared(Wh);
    const int arow = r0 + (lane & 15), acol8 = (lane >> 4) << 3;
    const int brow = (lane & 7) | ((lane & 16) >> 1), bcol8 = lane & 8;

    for (int p = 0; p < 3; ++p) {
        for (int i = tid * 4; i < 4096; i += 1024) {
            int r = i >> 6, c = i & 63;
            float4 x = *(const float4*)(Xsrc[p] +
                ((size_t)(n * L_SEQ + l0 + r)) * EMBED + h * HDIM + c);
            *(unsigned*)(Xh + r * XH_S + c)     = pack2(x.x, x.y);
            *(unsigned*)(Xh + r * XH_S + c + 2) = pack2(x.z, x.w);
            float4 w = *(const float4*)(Wsrc[p] + i);
            *(unsigned*)(Wh + r * XH_S + c)     = pack2(w.x, w.y);
            *(unsigned*)(Wh + r * XH_S + c + 2) = pack2(w.z, w.w);
        }
        __syncthreads();

        float acc[4][4] = {};
        #pragma unroll
        for (int kk = 0; kk < 4; ++kk) {
            unsigned a[4];
            ldm4(a, xh_u + (arow * XH_S + kk * 16 + acol8) * 2);
            #pragma unroll
            for (int jp = 0; jp < 2; ++jp) {
                unsigned b[4];
                ldm4(b, wh_u + ((n0 + jp * 16 + brow) * XH_S + kk * 16 + bcol8) * 2);
                mma16(acc[jp * 2],     a, b[0], b[1]);
                mma16(acc[jp * 2 + 1], a, b[2], b[3]);
            }
        }
        __syncthreads();

        const int r1 = r0 + grp, r2 = r1 + 8;
        #pragma unroll
        for (int nb = 0; nb < 4; ++nb) {
            const int c0 = n0 + nb * 8 + 2 * t;
            if (p == 0) {
                Ps[vb_off(r1, c0)]     = __float2half_rn(acc[nb][0]);
                Ps[vb_off(r1, c0 + 1)] = __float2half_rn(acc[nb][1]);
                Ps[vb_off(r2, c0)]     = __float2half_rn(acc[nb][2]);
                Ps[vb_off(r2, c0 + 1)] = __float2half_rn(acc[nb][3]);
            } else if (p == 1) {
                *(unsigned*)(Ps + kb_off(r1, c0)) = pack2(acc[nb][0], acc[nb][1]);
                *(unsigned*)(Ps + kb_off(r2, c0)) = pack2(acc[nb][2], acc[nb][3]);
            } else {
                *(unsigned*)(Ps + qa_off(r1, c0)) =
                    pack2(acc[nb][0] * QSCALE, acc[nb][1] * QSCALE);
                *(unsigned*)(Ps + qa_off(r2, c0)) =
                    pack2(acc[nb][2] * QSCALE, acc[nb][3] * QSCALE);
            }
        }
        __syncthreads();

        const size_t hb = (size_t)(n * NHEADS + h) * L_SEQ * HDIM;
        __half* dst;
        if (p == 0)      dst = g_v + hb + (size_t)lt * 4096;
        else if (p == 1) dst = g_k + hb + (size_t)lt * 4096;
        else             dst = g_q + hb + (size_t)(l0 >> 7) * 8192 + ((l0 & 64) ? 4096 : 0);
        for (int i = tid; i < 512; i += 256)
            ((uint4*)dst)[i] = ((const uint4*)Ps)[i];
        __syncthreads();
    }
}

// ---------------- kernel 2: fp16 flash attention (R11 schedule, best known) ---
// smem bytes: KB[3] 8192 each | VB[3] 8192 each = 49152
#define OFF_KB  0
#define OFF_VB  24576
#define ATTN_SMEM 49152

__global__ __launch_bounds__(64, 4) void attn_kernel(float* __restrict__ out)
{
    extern __shared__ char smc[];
    const int qt = blockIdx.x;            // 64-row tile index (0..31)
    const int h = blockIdx.y, n = blockIdx.z;
    const int qt128 = qt >> 1;
    const int tid = threadIdx.x, warp = tid >> 5, lane = tid & 31;
    const int grp = lane >> 2, t = lane & 3;
    const int bg0 = (qt & 1) * 4 + 2 * warp;   // first 16-row block id in qt128

    const __half* qg = g_q + ((size_t)(n * NHEADS + h) * 16 + qt128) * 8192;
    const __half* kg = g_k + (size_t)(n * NHEADS + h) * L_SEQ * HDIM;
    const __half* vg = g_v + (size_t)(n * NHEADS + h) * L_SEQ * HDIM;
    // mask fragments for this warp's two 16-row blocks (bg0, bg0+1)
    const uint4* mf0 = g_mf + ((size_t)(n * 16 + qt128) * 32 * 256 + bg0 * 32 + lane) * 4;
    const uint4* mf1 = mf0 + 32 * 4;

    const uint32_t sb = (uint32_t)__cvta_generic_to_shared(smc);

    // prologue: G0 = {K0, V0}; G1 = {K1, V1}   (64 threads x 8 uint4 = 512)
    #pragma unroll
    for (int j = 0; j < 8; ++j) {
        cpa16(sb + OFF_KB + (tid + j * 64) * 16, (const uint4*)kg + tid + j * 64);
        cpa16(sb + OFF_VB + (tid + j * 64) * 16, (const uint4*)vg + tid + j * 64);
    }
    CP_COMMIT();
    #pragma unroll
    for (int j = 0; j < 8; ++j) {
        cpa16(sb + OFF_KB + 8192 + (tid + j * 64) * 16, (const uint4*)(kg + 4096) + tid + j * 64);
        cpa16(sb + OFF_VB + 8192 + (tid + j * 64) * 16, (const uint4*)(vg + 4096) + tid + j * 64);
    }
    CP_COMMIT();

    // Q fragments for both row blocks (fragment-ordered gmem, one LDG pass)
    unsigned qa[2][4][4];
    #pragma unroll
    for (int b = 0; b < 2; ++b) {
        const uint4* qg4 = (const uint4*)qg + (bg0 + b) * 128 + lane;
        #pragma unroll
        for (int kk = 0; kk < 4; ++kk) {
            uint4 v = qg4[kk * 32];
            qa[b][kk][0] = v.x; qa[b][kk][1] = v.y; qa[b][kk][2] = v.z; qa[b][kk][3] = v.w;
        }
    }

    float o[2][8][4];
    #pragma unroll
    for (int b = 0; b < 2; ++b)
        #pragma unroll
        for (int j = 0; j < 8; ++j)
            o[b][j][0] = o[b][j][1] = o[b][j][2] = o[b][j][3] = 0.f;
    float ld[2][4] = {};

    int cur = 0, nxt = 2;
    for (int kti = 0; kti < NT; ++kti) {
        uint4 mk0[4], mk1[4];
        #pragma unroll
        for (int kk = 0; kk < 4; ++kk) {
            mk0[kk] = mf0[(size_t)kti * 1024 + kk];
            mk1[kk] = mf1[(size_t)kti * 1024 + kk];
        }

        CP_WAIT(1);
        __syncthreads();

        if (kti + 2 < NT) {
            const uint4* k2 = (const uint4*)(kg + (size_t)(kti + 2) * 4096);
            const uint4* v2 = (const uint4*)(vg + (size_t)(kti + 2) * 4096);
            const uint32_t kd = sb + OFF_KB + nxt * 8192;
            const uint32_t vd = sb + OFF_VB + nxt * 8192;
            #pragma unroll
            for (int j = 0; j < 8; ++j) {
                cpa16(kd + (tid + j * 64) * 16, k2 + tid + j * 64);
                cpa16(vd + (tid + j * 64) * 16, v2 + tid + j * 64);
            }
        }
        CP_COMMIT();

        const uint4* kb4 = (const uint4*)(smc + OFF_KB + cur * 8192) + lane;
        const uint4* vb4 = (const uint4*)(smc + OFF_VB + cur * 8192) + lane;

        // ---- S = Q K^T, fp16 accumulators; each K fragment feeds both blocks ----
        unsigned su[2][16];
        #pragma unroll
        for (int kk = 0; kk < 4; ++kk) {
            #pragma unroll
            for (int jp = 0; jp < 4; ++jp) {
                uint4 bv = kb4[kk * 128 + jp * 32];
                if (kk == 0) {
                    #pragma unroll
                    for (int b = 0; b < 2; ++b) {
                        mma16h_z(su[b][4 * jp],     su[b][4 * jp + 1], qa[b][0], bv.x, bv.y);
                        mma16h_z(su[b][4 * jp + 2], su[b][4 * jp + 3], qa[b][0], bv.z, bv.w);
                    }
                } else {
                    #pragma unroll
                    for (int b = 0; b < 2; ++b) {
                        mma16h(su[b][4 * jp],     su[b][4 * jp + 1], qa[b][kk], bv.x, bv.y);
                        mma16h(su[b][4 * jp + 2], su[b][4 * jp + 3], qa[b][kk], bv.z, bv.w);
                    }
                }
            }
        }

        // ---- p = 2^S, then AND-mask ----
        #pragma unroll
        for (int i = 0; i < 16; ++i) { ex2h2(su[0][i]); ex2h2(su[1][i]); }
        #pragma unroll
        for (int kk = 0; kk < 4; ++kk) {
            su[0][4 * kk]     &= mk0[kk].x; su[0][4 * kk + 1] &= mk0[kk].y;
            su[0][4 * kk + 2] &= mk0[kk].z; su[0][4 * kk + 3] &= mk0[kk].w;
            su[1][4 * kk]     &= mk1[kk].x; su[1][4 * kk + 1] &= mk1[kk].y;
            su[1][4 * kk + 2] &= mk1[kk].z; su[1][4 * kk + 3] &= mk1[kk].w;
        }

        // ---- O += P V ; row sums via ones-mma; V fragments shared across blocks ----
        #pragma unroll
        for (int kk = 0; kk < 4; ++kk) {
            #pragma unroll
            for (int jp = 0; jp < 4; ++jp) {
                uint4 bv = vb4[kk * 128 + jp * 32];
                #pragma unroll
                for (int b = 0; b < 2; ++b) {
                    mma16(o[b][jp * 2],     su[b] + 4 * kk, bv.x, bv.y);
                    mma16(o[b][jp * 2 + 1], su[b] + 4 * kk, bv.z, bv.w);
                }
            }
            mma16(ld[0], su[0] + 4 * kk, ONES2, ONES2);
            mma16(ld[1], su[1] + 4 * kk, ONES2, ONES2);
        }

        cur = (cur == 2) ? 0 : cur + 1;
        nxt = (nxt == 2) ? 0 : nxt + 1;
    }

    // ---- epilogue per row block ----
    const int q0 = qt128 * 128;
    #pragma unroll
    for (int b = 0; b < 2; ++b) {
        const int ra = (bg0 + b) * 16 + grp;
        const float inv1 = 1.f / ld[b][0], inv2 = 1.f / ld[b][2];
        float* ob1 = out + ((size_t)(n * L_SEQ + q0 + ra)) * EMBED + h * HDIM;
        float* ob2 = out + ((size_t)(n * L_SEQ + q0 + ra + 8)) * EMBED + h * HDIM;
        #pragma unroll
        for (int j = 0; j < 8; ++j) {
            int c0 = j * 8 + 2 * t;
            *(float2*)(ob1 + c0) = make_float2(o[b][j][0] * inv1, o[b][j][1] * inv1);
            *(float2*)(ob2 + c0) = make_float2(o[b][j][2] * inv2, o[b][j][3] * inv2);
        }
    }
}

// ---------------- launch ------------------------------------------------------
extern "C" void kernel_launch(void* const* d_in, const int* in_sizes, int n_in,
                              void* d_out, int out_size)
{
    const float* values  = (const float*)d_in[0];
    const float* keys    = (const float*)d_in[1];
    const float* queries = (const float*)d_in[2];
    const int*   mask    = (const int*)d_in[3];
    const float* Wv      = (const float*)d_in[4];
    const float* Wk      = (const float*)d_in[5];
    const float* Wq      = (const float*)d_in[6];
    float* out = (float*)d_out;

    cudaFuncSetAttribute(attn_kernel, cudaFuncAttributeMaxDynamicSharedMemorySize, ATTN_SMEM);

    proj_kernel<<<dim3(L_SEQ / 64, NHEADS, NBATCH), 256, PRJ_SMEM>>>(
        values, keys, queries, Wv, Wk, Wq, mask);
    attn_kernel<<<dim3(L_SEQ / 64, NHEADS, NBATCH), 64, ATTN_SMEM>>>(out);
}